// round 12
// baseline (speedup 1.0000x reference)
#include <cuda_runtime.h>
#include <cstdint>
#include <cstddef>

// ---------------- global accumulators (allocation-free scratch) -------------
__device__ double g_inter = 0.0;
__device__ double g_desire_sum = 0.0;
__device__ unsigned long long g_count = 0ull;
__device__ unsigned int g_ticket = 0u;

// ---------------- config ----------------------------------------------------
#define NST        5                 // pipeline stages
#define CH_ROWS    32                // rows per chunk
#define ROW_BYTES  512               // 128 fp32
#define O_BYTES    (CH_ROWS * ROW_BYTES)      // 16384 per input per chunk
#define D_BYTES    (CH_ROWS * 4)              // 128   desire per chunk
#define STAGE_STRIDE (2 * O_BYTES + D_BYTES)  // 32896 (multiple of 128)
#define SMEM_DYN   (NST * STAGE_STRIDE)       // 164480 B
#define THREADS    512

// ---------------- PTX helpers ----------------------------------------------
__device__ __forceinline__ uint32_t s2u(const void* p) {
    uint32_t a;
    asm("{ .reg .u64 t; cvta.to.shared.u64 t, %1; cvt.u32.u64 %0, t; }"
        : "=r"(a) : "l"(p));
    return a;
}
__device__ __forceinline__ void mbar_init(uint32_t m, uint32_t cnt) {
    asm volatile("mbarrier.init.shared.b64 [%0], %1;" :: "r"(m), "r"(cnt) : "memory");
}
__device__ __forceinline__ void mbar_expect_tx(uint32_t m, uint32_t tx) {
    asm volatile("mbarrier.arrive.expect_tx.shared.b64 _, [%0], %1;"
                 :: "r"(m), "r"(tx) : "memory");
}
__device__ __forceinline__ void bulk_g2s(uint32_t dst, const void* src,
                                         uint32_t bytes, uint32_t m) {
    asm volatile(
        "cp.async.bulk.shared::cluster.global.mbarrier::complete_tx::bytes "
        "[%0], [%1], %2, [%3];"
        :: "r"(dst), "l"(src), "r"(bytes), "r"(m) : "memory");
}
__device__ __forceinline__ void mbar_wait(uint32_t m, uint32_t ph) {
    uint32_t done;
    asm volatile(
        "{\n\t.reg .pred p;\n\t"
        "mbarrier.try_wait.parity.acquire.cta.shared::cta.b64 p, [%1], %2;\n\t"
        "selp.b32 %0, 1, 0, p;\n\t}"
        : "=r"(done) : "r"(m), "r"(ph) : "memory");
    while (!done) {
        asm volatile(
            "{\n\t.reg .pred p;\n\t"
            "mbarrier.try_wait.parity.acquire.cta.shared::cta.b64 p, [%1], %2, 0x989680;\n\t"
            "selp.b32 %0, 1, 0, p;\n\t}"
            : "=r"(done) : "r"(m), "r"(ph) : "memory");
    }
}

// ---------------- kernel -----------------------------------------------------
// Persistent 1 block/SM. Thread 0 drives a 5-stage bulk-async (TMA) ring:
// each stage holds a 32-row chunk of o1+o2+desire. All 512 threads drain a
// stage from smem: 16 lanes per row (2x float4 per input per thread), 4-deep
// shuffle reduce, j==0 lane accumulates. DRAM requests are now engine-driven
// 16KB sequential bursts instead of per-lane LDG.128 swarms.
__global__ __launch_bounds__(THREADS, 1)
void fra_tma_kernel(const char* __restrict__ o1b,
                    const char* __restrict__ o2b,
                    const char* __restrict__ desb,
                    float* __restrict__ out,
                    int n_rows) {
    extern __shared__ char smem[];
    __shared__ unsigned long long mbar_store[NST];
    __shared__ double       s_i[16], s_d[16];
    __shared__ unsigned int s_c[16];
    __shared__ bool         s_last;

    const int tid  = threadIdx.x;
    const int row  = tid >> 4;          // 0..31 within chunk
    const int j    = tid & 15;          // float4 slots j and j+16 of the row
    const int lane = tid & 31;
    const int wib  = tid >> 5;          // 0..15

    const uint32_t smem_base = s2u(smem);
    uint32_t mb[NST];
    #pragma unroll
    for (int s = 0; s < NST; s++) mb[s] = s2u(&mbar_store[s]);

    if (tid == 0) {
        #pragma unroll
        for (int s = 0; s < NST; s++) mbar_init(mb[s], 1);
    }
    __syncthreads();

    const int nchunks = n_rows >> 5;    // 32 rows per chunk

    // Prologue: fill the ring.
    if (tid == 0) {
        for (int s = 0; s < NST; s++) {
            const int c = blockIdx.x + s * gridDim.x;
            if (c < nchunks) {
                mbar_expect_tx(mb[s], 2 * O_BYTES + D_BYTES);
                const uint32_t sb = smem_base + s * STAGE_STRIDE;
                bulk_g2s(sb,               o1b  + (size_t)c * O_BYTES, O_BYTES, mb[s]);
                bulk_g2s(sb + O_BYTES,     o2b  + (size_t)c * O_BYTES, O_BYTES, mb[s]);
                bulk_g2s(sb + 2 * O_BYTES, desb + (size_t)c * D_BYTES, D_BYTES, mb[s]);
            }
        }
    }

    double       l_inter = 0.0, l_des = 0.0;
    unsigned int l_cnt = 0u;
    const float margin_sq = 0.390625f;  // (1.25/2)^2

    int it = 0;
    for (int c = blockIdx.x; c < nchunks; c += gridDim.x, it++) {
        const int      st = it % NST;
        const uint32_t ph = (uint32_t)((it / NST) & 1);
        mbar_wait(mb[st], ph);

        const char* stage = smem + st * STAGE_STRIDE;
        const float4* p1 = (const float4*)(stage)            + row * 32 + j;
        const float4* p2 = (const float4*)(stage + O_BYTES)  + row * 32 + j;
        const float*  pd = (const float*) (stage + 2 * O_BYTES);

        const float4 a0 = p1[0],  a1 = p1[16];
        const float4 b0 = p2[0],  b1 = p2[16];

        float s0, s1, d;
        d = a0.x - b0.x; s0  = d * d;   d = a0.y - b0.y; s1  = d * d;
        d = a0.z - b0.z; s0 += d * d;   d = a0.w - b0.w; s1 += d * d;
        d = a1.x - b1.x; s0 += d * d;   d = a1.y - b1.y; s1 += d * d;
        d = a1.z - b1.z; s0 += d * d;   d = a1.w - b1.w; s1 += d * d;
        float s = s0 + s1;

        // Reduce across the 16 lanes of this row.
        s += __shfl_xor_sync(0xffffffffu, s, 8);
        s += __shfl_xor_sync(0xffffffffu, s, 4);
        s += __shfl_xor_sync(0xffffffffu, s, 2);
        s += __shfl_xor_sync(0xffffffffu, s, 1);

        if (j == 0) {
            const float dsr = pd[row];
            l_des += (double)dsr;
            if (s > margin_sq) { l_cnt += 1u; l_inter += (double)dsr; }
        }

        __syncthreads();   // everyone done reading this stage

        if (tid == 0) {
            const int nc = c + NST * gridDim.x;
            if (nc < nchunks) {
                mbar_expect_tx(mb[st], 2 * O_BYTES + D_BYTES);
                const uint32_t sb = smem_base + st * STAGE_STRIDE;
                bulk_g2s(sb,               o1b  + (size_t)nc * O_BYTES, O_BYTES, mb[st]);
                bulk_g2s(sb + O_BYTES,     o2b  + (size_t)nc * O_BYTES, O_BYTES, mb[st]);
                bulk_g2s(sb + 2 * O_BYTES, desb + (size_t)nc * D_BYTES, D_BYTES, mb[st]);
            }
        }
    }

    // Tail rows (n_rows % 32) — block 0, direct gmem loads. Empty for N=2^18.
    if (blockIdx.x == 0) {
        const float4* o1 = (const float4*)o1b;
        const float4* o2 = (const float4*)o2b;
        const float*  de = (const float*)desb;
        for (int r0 = nchunks * CH_ROWS; r0 < n_rows; r0 += CH_ROWS) {
            const int r = r0 + row;
            float s = 0.0f;
            if (r < n_rows) {
                const int base = r * 32 + j;
                const float4 a0 = o1[base], a1 = o1[base + 16];
                const float4 b0 = o2[base], b1 = o2[base + 16];
                float dx;
                dx = a0.x - b0.x; s += dx * dx;  dx = a0.y - b0.y; s += dx * dx;
                dx = a0.z - b0.z; s += dx * dx;  dx = a0.w - b0.w; s += dx * dx;
                dx = a1.x - b1.x; s += dx * dx;  dx = a1.y - b1.y; s += dx * dx;
                dx = a1.z - b1.z; s += dx * dx;  dx = a1.w - b1.w; s += dx * dx;
            }
            s += __shfl_xor_sync(0xffffffffu, s, 8);
            s += __shfl_xor_sync(0xffffffffu, s, 4);
            s += __shfl_xor_sync(0xffffffffu, s, 2);
            s += __shfl_xor_sync(0xffffffffu, s, 1);
            if (j == 0 && r < n_rows) {
                const float dsr = de[r];
                l_des += (double)dsr;
                if (s > margin_sq) { l_cnt += 1u; l_inter += (double)dsr; }
            }
        }
    }

    // Warp reduction (j==0 lanes hold data; reduce all 32 lanes).
    #pragma unroll
    for (int off = 16; off > 0; off >>= 1) {
        l_inter += __shfl_xor_sync(0xffffffffu, l_inter, off);
        l_des   += __shfl_xor_sync(0xffffffffu, l_des,   off);
        l_cnt   += __shfl_xor_sync(0xffffffffu, l_cnt,   off);
    }
    if (lane == 0) { s_i[wib] = l_inter; s_d[wib] = l_des; s_c[wib] = l_cnt; }
    __syncthreads();

    if (tid == 0) {
        double       bi = 0.0, bd = 0.0;
        unsigned int bc = 0u;
        #pragma unroll
        for (int w = 0; w < 16; w++) { bi += s_i[w]; bd += s_d[w]; bc += s_c[w]; }
        atomicAdd(&g_inter, bi);
        atomicAdd(&g_desire_sum, bd);
        atomicAdd(&g_count, (unsigned long long)bc);
        __threadfence();
        s_last = (atomicAdd(&g_ticket, 1u) == gridDim.x - 1);
    }
    __syncthreads();

    if (s_last && tid == 0) {
        __threadfence();
        const double inter = atomicAdd(&g_inter, 0.0);
        const double des   = atomicAdd(&g_desire_sum, 0.0);
        const double cnt   = (double)atomicAdd(&g_count, 0ull);
        const double uni   = cnt + des - inter;
        out[0] = (float)((inter + 1e-6) / (uni + 1e-6));
        g_inter = 0.0;
        g_desire_sum = 0.0;
        g_count = 0ull;
        __threadfence();
        g_ticket = 0u;
    }
}

// ---------------- launch -----------------------------------------------------
extern "C" void kernel_launch(void* const* d_in, const int* in_sizes, int n_in,
                              void* d_out, int out_size) {
    const char* o1  = (const char*)d_in[0];
    const char* o2  = (const char*)d_in[1];
    const char* des = (const char*)d_in[2];
    float*      out = (float*)d_out;

    const int n_rows = in_sizes[2];   // N = 262144

    // Opt-in to >48KB dynamic smem (attribute set is not an allocation and is
    // idempotent; executed immediately even under capture).
    cudaFuncSetAttribute(fra_tma_kernel,
                         cudaFuncAttributeMaxDynamicSharedMemorySize, SMEM_DYN);

    // 148 blocks = 1 per SM, persistent; 8192 chunks grid-strided.
    fra_tma_kernel<<<148, THREADS, SMEM_DYN>>>(o1, o2, des, out, n_rows);
}

// round 14
// speedup vs baseline: 2.3699x; 2.3699x over previous
#include <cuda_runtime.h>

// ---------------- global accumulators (allocation-free scratch) -------------
__device__ double g_inter = 0.0;
__device__ double g_desire_sum = 0.0;
__device__ unsigned long long g_count = 0ull;
__device__ unsigned int g_ticket = 0u;

// Key idea: dist^2 is a sum of squares -> partial sums are monotone.
// If the first-32-column partial already exceeds margin^2, the row is
// classified with certainty. Only rows whose partial is <= margin^2 need the
// remaining 96 columns (rare-to-never for this data; handled exactly by a
// fallback path, so the kernel is correct for ANY input).
// Traffic: 68 MB instead of 269 MB. Each row's first 128B is one full,
// aligned 128B line -> every fetched line is 100% used.

#define MARGIN_SQ 0.390625f   // (1.25/2)^2

// Load the first-128B slice of a 16-row tile: group g (8 lanes) owns rows
// tile*16+g*4 .. +3; lane j loads float4 slot j (j<8 -> cols 0..31).
#define LOAD16(T, A, B)                                                   \
    do {                                                                  \
        if ((T) < n_t16) {                                                \
            const int _r = (T) * 16 + g * 4;                              \
            const int _b = _r * 32 + j;                                   \
            A[0] = o1[_b];      B[0] = o2[_b];                            \
            A[1] = o1[_b + 32]; B[1] = o2[_b + 32];                       \
            A[2] = o1[_b + 64]; B[2] = o2[_b + 64];                       \
            A[3] = o1[_b + 96]; B[3] = o2[_b + 96];                       \
        }                                                                 \
    } while (0)

__global__ __launch_bounds__(256, 2)
void fra_partial_kernel(const float4* __restrict__ o1,
                        const float4* __restrict__ o2,
                        const float4* __restrict__ des4,
                        const float*  __restrict__ des,
                        float* __restrict__ out,
                        int n_rows) {
    const int lane = threadIdx.x & 31;
    const int wib  = threadIdx.x >> 5;
    const int wpb  = blockDim.x >> 5;
    const int wg   = blockIdx.x * wpb + wib;
    const int tw   = gridDim.x * wpb;

    const int g = lane >> 3;   // 8-lane group: rows tile*16+g*4 .. +3
    const int j = lane & 7;    // float4 slot 0..7 (columns 4j..4j+3)

    double       l_inter = 0.0, l_des = 0.0;
    unsigned int l_cnt = 0u;

    const int n_t16 = n_rows >> 4;   // 16-row tiles

    float4 aA[4], bA[4], aB[4], bB[4];

    int t = wg;
    LOAD16(t, aA, bA);

    while (t < n_t16) {
        // ---- stage A compute, prefetch into B first ----
        int nx = t + tw;
        LOAD16(nx, aB, bB);
        {
            float s[4];
            #pragma unroll
            for (int k = 0; k < 4; k++) {
                float dx = aA[k].x - bA[k].x; float acc = dx * dx;
                dx = aA[k].y - bA[k].y; acc += dx * dx;
                dx = aA[k].z - bA[k].z; acc += dx * dx;
                dx = aA[k].w - bA[k].w; acc += dx * dx;
                s[k] = acc;
            }
            #pragma unroll
            for (int off = 4; off > 0; off >>= 1)
                #pragma unroll
                for (int k = 0; k < 4; k++)
                    s[k] += __shfl_xor_sync(0xffffffffu, s[k], off);

            // Rare exact fallback: any row whose 32-col partial is under
            // the threshold gets the remaining 96 columns.
            const bool need = (s[0] <= MARGIN_SQ) | (s[1] <= MARGIN_SQ) |
                              (s[2] <= MARGIN_SQ) | (s[3] <= MARGIN_SQ);
            if (__ballot_sync(0xffffffffu, need)) {
                const int r = t * 16 + g * 4;
                #pragma unroll
                for (int k = 0; k < 4; k++) {
                    float e = 0.0f;
                    #pragma unroll
                    for (int m = 1; m < 4; m++) {
                        const float4 a = o1[(r + k) * 32 + j + 8 * m];
                        const float4 b = o2[(r + k) * 32 + j + 8 * m];
                        float dx = a.x - b.x; e += dx * dx;
                        dx = a.y - b.y; e += dx * dx;
                        dx = a.z - b.z; e += dx * dx;
                        dx = a.w - b.w; e += dx * dx;
                    }
                    #pragma unroll
                    for (int off = 4; off > 0; off >>= 1)
                        e += __shfl_xor_sync(0xffffffffu, e, off);
                    s[k] += e;
                }
            }

            if (j == 0) {
                const float4 dv = des4[t * 4 + g];
                const float dk[4] = {dv.x, dv.y, dv.z, dv.w};
                #pragma unroll
                for (int k = 0; k < 4; k++) {
                    l_des += (double)dk[k];
                    if (s[k] > MARGIN_SQ) { l_cnt += 1u; l_inter += (double)dk[k]; }
                }
            }
        }
        t = nx;
        if (t >= n_t16) break;

        // ---- stage B compute, prefetch into A first ----
        nx = t + tw;
        LOAD16(nx, aA, bA);
        {
            float s[4];
            #pragma unroll
            for (int k = 0; k < 4; k++) {
                float dx = aB[k].x - bB[k].x; float acc = dx * dx;
                dx = aB[k].y - bB[k].y; acc += dx * dx;
                dx = aB[k].z - bB[k].z; acc += dx * dx;
                dx = aB[k].w - bB[k].w; acc += dx * dx;
                s[k] = acc;
            }
            #pragma unroll
            for (int off = 4; off > 0; off >>= 1)
                #pragma unroll
                for (int k = 0; k < 4; k++)
                    s[k] += __shfl_xor_sync(0xffffffffu, s[k], off);

            const bool need = (s[0] <= MARGIN_SQ) | (s[1] <= MARGIN_SQ) |
                              (s[2] <= MARGIN_SQ) | (s[3] <= MARGIN_SQ);
            if (__ballot_sync(0xffffffffu, need)) {
                const int r = t * 16 + g * 4;
                #pragma unroll
                for (int k = 0; k < 4; k++) {
                    float e = 0.0f;
                    #pragma unroll
                    for (int m = 1; m < 4; m++) {
                        const float4 a = o1[(r + k) * 32 + j + 8 * m];
                        const float4 b = o2[(r + k) * 32 + j + 8 * m];
                        float dx = a.x - b.x; e += dx * dx;
                        dx = a.y - b.y; e += dx * dx;
                        dx = a.z - b.z; e += dx * dx;
                        dx = a.w - b.w; e += dx * dx;
                    }
                    #pragma unroll
                    for (int off = 4; off > 0; off >>= 1)
                        e += __shfl_xor_sync(0xffffffffu, e, off);
                    s[k] += e;
                }
            }

            if (j == 0) {
                const float4 dv = des4[t * 4 + g];
                const float dk[4] = {dv.x, dv.y, dv.z, dv.w};
                #pragma unroll
                for (int k = 0; k < 4; k++) {
                    l_des += (double)dk[k];
                    if (s[k] > MARGIN_SQ) { l_cnt += 1u; l_inter += (double)dk[k]; }
                }
            }
        }
        t = nx;
    }

    // Tail rows (n_rows % 16): warp 0, full 128-column exact compute.
    if (wg == 0) {
        for (int row = n_t16 * 16; row < n_rows; row++) {
            float s = 0.0f;
            if (g == 0) {
                const int base = row * 32 + j;
                #pragma unroll
                for (int m = 0; m < 4; m++) {
                    const float4 a = o1[base + 8 * m];
                    const float4 b = o2[base + 8 * m];
                    float dx = a.x - b.x; s += dx * dx;
                    dx = a.y - b.y; s += dx * dx;
                    dx = a.z - b.z; s += dx * dx;
                    dx = a.w - b.w; s += dx * dx;
                }
            }
            #pragma unroll
            for (int off = 4; off > 0; off >>= 1)
                s += __shfl_xor_sync(0xffffffffu, s, off);
            if (lane == 0) {
                const float dsr = des[row];
                l_des += (double)dsr;
                if (s > MARGIN_SQ) { l_cnt += 1u; l_inter += (double)dsr; }
            }
        }
    }

    // Warp reduction (accumulators live on j==0 lanes; reduce all 32).
    #pragma unroll
    for (int off = 16; off > 0; off >>= 1) {
        l_inter += __shfl_xor_sync(0xffffffffu, l_inter, off);
        l_des   += __shfl_xor_sync(0xffffffffu, l_des,   off);
        l_cnt   += __shfl_xor_sync(0xffffffffu, l_cnt,   off);
    }

    __shared__ double       s_i[8], s_d[8];
    __shared__ unsigned int s_c[8];
    __shared__ bool         s_last;
    if (lane == 0) { s_i[wib] = l_inter; s_d[wib] = l_des; s_c[wib] = l_cnt; }
    __syncthreads();

    if (threadIdx.x == 0) {
        double       bi = 0.0, bd = 0.0;
        unsigned int bc = 0u;
        for (int w = 0; w < wpb; w++) { bi += s_i[w]; bd += s_d[w]; bc += s_c[w]; }
        atomicAdd(&g_inter, bi);
        atomicAdd(&g_desire_sum, bd);
        atomicAdd(&g_count, (unsigned long long)bc);
        __threadfence();
        s_last = (atomicAdd(&g_ticket, 1u) == gridDim.x - 1);
    }
    __syncthreads();

    if (s_last && threadIdx.x == 0) {
        __threadfence();
        const double inter = atomicAdd(&g_inter, 0.0);
        const double dsum  = atomicAdd(&g_desire_sum, 0.0);
        const double cnt   = (double)atomicAdd(&g_count, 0ull);
        const double uni   = cnt + dsum - inter;
        out[0] = (float)((inter + 1e-6) / (uni + 1e-6));
        g_inter = 0.0;
        g_desire_sum = 0.0;
        g_count = 0ull;
        __threadfence();
        g_ticket = 0u;
    }
}

extern "C" void kernel_launch(void* const* d_in, const int* in_sizes, int n_in,
                              void* d_out, int out_size) {
    const float4* o1   = (const float4*)d_in[0];
    const float4* o2   = (const float4*)d_in[1];
    const float*  des  = (const float*)d_in[2];
    float*        out  = (float*)d_out;

    const int n_rows = in_sizes[2];   // N = 262144

    // Proven R8 shape: 296 = 148 SMs x 2 blocks, 256 threads, one wave.
    fra_partial_kernel<<<296, 256>>>(o1, o2, (const float4*)des, des, out, n_rows);
}

// round 15
// speedup vs baseline: 2.4028x; 1.0139x over previous
#include <cuda_runtime.h>

// ---------------- global accumulators (allocation-free scratch) -------------
__device__ double g_inter = 0.0;
__device__ double g_desire_sum = 0.0;
__device__ unsigned long long g_count = 0ull;
__device__ unsigned int g_ticket = 0u;

// Key idea: dist^2 is a sum of squares -> partial sums are monotone.
// If the first-32-column partial already exceeds margin^2, the row is
// classified with certainty. Only rows whose partial is <= margin^2 need the
// remaining 96 columns (rare-to-never for this data; handled exactly by a
// fallback path, so the kernel is correct for ANY input).
// Traffic: 68 MB instead of 269 MB. Each row's first 128B is one full,
// aligned 128B line -> every fetched line is 100% used.

#define MARGIN_SQ 0.390625f   // (1.25/2)^2

// Load the first-128B slice of a 16-row tile: group g (8 lanes) owns rows
// tile*16+g*4 .. +3; lane j loads float4 slot j (j<8 -> cols 0..31).
#define LOAD16(T, A, B)                                                   \
    do {                                                                  \
        if ((T) < n_t16) {                                                \
            const int _r = (T) * 16 + g * 4;                              \
            const int _b = _r * 32 + j;                                   \
            A[0] = o1[_b];      B[0] = o2[_b];                            \
            A[1] = o1[_b + 32]; B[1] = o2[_b + 32];                       \
            A[2] = o1[_b + 64]; B[2] = o2[_b + 64];                       \
            A[3] = o1[_b + 96]; B[3] = o2[_b + 96];                       \
        }                                                                 \
    } while (0)

__global__ __launch_bounds__(256, 2)
void fra_partial_kernel(const float4* __restrict__ o1,
                        const float4* __restrict__ o2,
                        const float4* __restrict__ des4,
                        const float*  __restrict__ des,
                        float* __restrict__ out,
                        int n_rows) {
    const int lane = threadIdx.x & 31;
    const int wib  = threadIdx.x >> 5;
    const int wpb  = blockDim.x >> 5;
    const int wg   = blockIdx.x * wpb + wib;
    const int tw   = gridDim.x * wpb;

    const int g = lane >> 3;   // 8-lane group: rows tile*16+g*4 .. +3
    const int j = lane & 7;    // float4 slot 0..7 (columns 4j..4j+3)

    double       l_inter = 0.0, l_des = 0.0;
    unsigned int l_cnt = 0u;

    const int n_t16 = n_rows >> 4;   // 16-row tiles

    float4 aA[4], bA[4], aB[4], bB[4];

    int t = wg;
    LOAD16(t, aA, bA);

    while (t < n_t16) {
        // ---- stage A compute, prefetch into B first ----
        int nx = t + tw;
        LOAD16(nx, aB, bB);
        {
            float s[4];
            #pragma unroll
            for (int k = 0; k < 4; k++) {
                float dx = aA[k].x - bA[k].x; float acc = dx * dx;
                dx = aA[k].y - bA[k].y; acc += dx * dx;
                dx = aA[k].z - bA[k].z; acc += dx * dx;
                dx = aA[k].w - bA[k].w; acc += dx * dx;
                s[k] = acc;
            }
            #pragma unroll
            for (int off = 4; off > 0; off >>= 1)
                #pragma unroll
                for (int k = 0; k < 4; k++)
                    s[k] += __shfl_xor_sync(0xffffffffu, s[k], off);

            // Rare exact fallback: any row whose 32-col partial is under
            // the threshold gets the remaining 96 columns.
            const bool need = (s[0] <= MARGIN_SQ) | (s[1] <= MARGIN_SQ) |
                              (s[2] <= MARGIN_SQ) | (s[3] <= MARGIN_SQ);
            if (__ballot_sync(0xffffffffu, need)) {
                const int r = t * 16 + g * 4;
                #pragma unroll
                for (int k = 0; k < 4; k++) {
                    float e = 0.0f;
                    #pragma unroll
                    for (int m = 1; m < 4; m++) {
                        const float4 a = o1[(r + k) * 32 + j + 8 * m];
                        const float4 b = o2[(r + k) * 32 + j + 8 * m];
                        float dx = a.x - b.x; e += dx * dx;
                        dx = a.y - b.y; e += dx * dx;
                        dx = a.z - b.z; e += dx * dx;
                        dx = a.w - b.w; e += dx * dx;
                    }
                    #pragma unroll
                    for (int off = 4; off > 0; off >>= 1)
                        e += __shfl_xor_sync(0xffffffffu, e, off);
                    s[k] += e;
                }
            }

            if (j == 0) {
                const float4 dv = des4[t * 4 + g];
                const float dk[4] = {dv.x, dv.y, dv.z, dv.w};
                #pragma unroll
                for (int k = 0; k < 4; k++) {
                    l_des += (double)dk[k];
                    if (s[k] > MARGIN_SQ) { l_cnt += 1u; l_inter += (double)dk[k]; }
                }
            }
        }
        t = nx;
        if (t >= n_t16) break;

        // ---- stage B compute, prefetch into A first ----
        nx = t + tw;
        LOAD16(nx, aA, bA);
        {
            float s[4];
            #pragma unroll
            for (int k = 0; k < 4; k++) {
                float dx = aB[k].x - bB[k].x; float acc = dx * dx;
                dx = aB[k].y - bB[k].y; acc += dx * dx;
                dx = aB[k].z - bB[k].z; acc += dx * dx;
                dx = aB[k].w - bB[k].w; acc += dx * dx;
                s[k] = acc;
            }
            #pragma unroll
            for (int off = 4; off > 0; off >>= 1)
                #pragma unroll
                for (int k = 0; k < 4; k++)
                    s[k] += __shfl_xor_sync(0xffffffffu, s[k], off);

            const bool need = (s[0] <= MARGIN_SQ) | (s[1] <= MARGIN_SQ) |
                              (s[2] <= MARGIN_SQ) | (s[3] <= MARGIN_SQ);
            if (__ballot_sync(0xffffffffu, need)) {
                const int r = t * 16 + g * 4;
                #pragma unroll
                for (int k = 0; k < 4; k++) {
                    float e = 0.0f;
                    #pragma unroll
                    for (int m = 1; m < 4; m++) {
                        const float4 a = o1[(r + k) * 32 + j + 8 * m];
                        const float4 b = o2[(r + k) * 32 + j + 8 * m];
                        float dx = a.x - b.x; e += dx * dx;
                        dx = a.y - b.y; e += dx * dx;
                        dx = a.z - b.z; e += dx * dx;
                        dx = a.w - b.w; e += dx * dx;
                    }
                    #pragma unroll
                    for (int off = 4; off > 0; off >>= 1)
                        e += __shfl_xor_sync(0xffffffffu, e, off);
                    s[k] += e;
                }
            }

            if (j == 0) {
                const float4 dv = des4[t * 4 + g];
                const float dk[4] = {dv.x, dv.y, dv.z, dv.w};
                #pragma unroll
                for (int k = 0; k < 4; k++) {
                    l_des += (double)dk[k];
                    if (s[k] > MARGIN_SQ) { l_cnt += 1u; l_inter += (double)dk[k]; }
                }
            }
        }
        t = nx;
    }

    // Tail rows (n_rows % 16): warp 0, full 128-column exact compute.
    if (wg == 0) {
        for (int row = n_t16 * 16; row < n_rows; row++) {
            float s = 0.0f;
            if (g == 0) {
                const int base = row * 32 + j;
                #pragma unroll
                for (int m = 0; m < 4; m++) {
                    const float4 a = o1[base + 8 * m];
                    const float4 b = o2[base + 8 * m];
                    float dx = a.x - b.x; s += dx * dx;
                    dx = a.y - b.y; s += dx * dx;
                    dx = a.z - b.z; s += dx * dx;
                    dx = a.w - b.w; s += dx * dx;
                }
            }
            #pragma unroll
            for (int off = 4; off > 0; off >>= 1)
                s += __shfl_xor_sync(0xffffffffu, s, off);
            if (lane == 0) {
                const float dsr = des[row];
                l_des += (double)dsr;
                if (s > MARGIN_SQ) { l_cnt += 1u; l_inter += (double)dsr; }
            }
        }
    }

    // Warp reduction (accumulators live on j==0 lanes; reduce all 32).
    #pragma unroll
    for (int off = 16; off > 0; off >>= 1) {
        l_inter += __shfl_xor_sync(0xffffffffu, l_inter, off);
        l_des   += __shfl_xor_sync(0xffffffffu, l_des,   off);
        l_cnt   += __shfl_xor_sync(0xffffffffu, l_cnt,   off);
    }

    __shared__ double       s_i[8], s_d[8];
    __shared__ unsigned int s_c[8];
    __shared__ bool         s_last;
    if (lane == 0) { s_i[wib] = l_inter; s_d[wib] = l_des; s_c[wib] = l_cnt; }
    __syncthreads();

    if (threadIdx.x == 0) {
        double       bi = 0.0, bd = 0.0;
        unsigned int bc = 0u;
        for (int w = 0; w < wpb; w++) { bi += s_i[w]; bd += s_d[w]; bc += s_c[w]; }
        atomicAdd(&g_inter, bi);
        atomicAdd(&g_desire_sum, bd);
        atomicAdd(&g_count, (unsigned long long)bc);
        __threadfence();
        s_last = (atomicAdd(&g_ticket, 1u) == gridDim.x - 1);
    }
    __syncthreads();

    if (s_last && threadIdx.x == 0) {
        __threadfence();
        const double inter = atomicAdd(&g_inter, 0.0);
        const double dsum  = atomicAdd(&g_desire_sum, 0.0);
        const double cnt   = (double)atomicAdd(&g_count, 0ull);
        const double uni   = cnt + dsum - inter;
        out[0] = (float)((inter + 1e-6) / (uni + 1e-6));
        g_inter = 0.0;
        g_desire_sum = 0.0;
        g_count = 0ull;
        __threadfence();
        g_ticket = 0u;
    }
}

extern "C" void kernel_launch(void* const* d_in, const int* in_sizes, int n_in,
                              void* d_out, int out_size) {
    const float4* o1   = (const float4*)d_in[0];
    const float4* o2   = (const float4*)d_in[1];
    const float*  des  = (const float*)d_in[2];
    float*        out  = (float*)d_out;

    const int n_rows = in_sizes[2];   // N = 262144

    // Proven R8 shape: 296 = 148 SMs x 2 blocks, 256 threads, one wave.
    fra_partial_kernel<<<296, 256>>>(o1, o2, (const float4*)des, des, out, n_rows);
}